// round 5
// baseline (speedup 1.0000x reference)
#include <cuda_runtime.h>
#include <cuda_bf16.h>

// Survival cross-entropy loss:
//   h = clamp(preds, 1e-9, 1-1e-9); lg = log1p(-h)
//   pre_incl = sum_{j<=t} lg[j]
//   loss_i = event ? -(pre_incl - lg_t) - log(h_t) : -pre_incl
//   out = sum(loss_i) / n
//
// Per-element form used here:
//   loss_i = sum_{j<=t} (-lg[j])  +  (event ? (lg_t - log(h_t)) : 0)
//
// NOTE: targets come from JAX with x64 disabled -> they are int32 pairs
// (duration, event) per row, NOT int64.
//
// One warp per row (T=64, lane owns 2 contiguous columns via float2).
// Loads for columns > t are predicated off -> ~44% of pred bytes skipped
// at 32B sector granularity.

#define THREADS 256
#define WARPS_PER_BLOCK (THREADS / 32)
#define MAX_BLOCKS 131072

__device__ float g_partials[MAX_BLOCKS];

__global__ void __launch_bounds__(THREADS)
survival_loss_kernel(const float* __restrict__ preds,
                     const int2* __restrict__ targets,
                     int n, int total_warps)
{
    const int lane    = threadIdx.x & 31;
    const int warp_in = threadIdx.x >> 5;
    int warp_id = (blockIdx.x * WARPS_PER_BLOCK) + warp_in;

    float lane_val = 0.0f;

    // grid-stride over rows (one warp = one row)
    for (int row = warp_id; row < n; row += total_warps) {
        // lane 0 loads the (duration, event) pair, broadcast to the warp
        int t_raw = 0, e_raw = 0;
        if (lane == 0) {
            int2 te = targets[row];
            t_raw = te.x;
            e_raw = te.y;
        }
        t_raw = __shfl_sync(0xFFFFFFFFu, t_raw, 0);
        e_raw = __shfl_sync(0xFFFFFFFFu, e_raw, 0);

        int  t  = min(max(t_raw, 0), 63);
        bool ev = (e_raw != 0);

        const int c0 = lane * 2;

        if (c0 <= t) {
            // c0 even, <= 62 here, so c0+1 <= 63 is always a valid column
            float2 v = *(const float2*)(preds + (long long)row * 64 + c0);

            float h0  = fminf(fmaxf(v.x, 1e-9f), 0.99999994f);
            float lg0 = __logf(1.0f - h0);
            float h1  = fminf(fmaxf(v.y, 1e-9f), 0.99999994f);
            float lg1 = __logf(1.0f - h1);

            float contrib = -lg0;                  // j = c0 (always <= t here)
            if (c0 + 1 <= t) contrib -= lg1;       // j = c0+1

            if (ev) {
                if (c0 == t)          contrib += lg0 - __logf(h0);
                else if (c0 + 1 == t) contrib += lg1 - __logf(h1);
            }
            lane_val += contrib;
        }
    }

    // warp reduction
    #pragma unroll
    for (int off = 16; off > 0; off >>= 1)
        lane_val += __shfl_xor_sync(0xFFFFFFFFu, lane_val, off);

    __shared__ float warp_sums[WARPS_PER_BLOCK];
    if (lane == 0) warp_sums[warp_in] = lane_val;
    __syncthreads();

    // deterministic per-block partial (single thread, fixed order)
    if (threadIdx.x == 0) {
        float s = 0.0f;
        #pragma unroll
        for (int i = 0; i < WARPS_PER_BLOCK; i++) s += warp_sums[i];
        g_partials[blockIdx.x] = s;
    }
}

__global__ void __launch_bounds__(1024)
survival_loss_reduce(float* __restrict__ out, int num_blocks, int n)
{
    __shared__ double sh[1024];
    double s = 0.0;
    for (int i = threadIdx.x; i < num_blocks; i += 1024)
        s += (double)g_partials[i];
    sh[threadIdx.x] = s;
    __syncthreads();
    #pragma unroll
    for (int off = 512; off > 0; off >>= 1) {
        if (threadIdx.x < off) sh[threadIdx.x] += sh[threadIdx.x + off];
        __syncthreads();
    }
    if (threadIdx.x == 0)
        out[0] = (float)(sh[0] / (double)n);
}

extern "C" void kernel_launch(void* const* d_in, const int* in_sizes, int n_in,
                              void* d_out, int out_size)
{
    // Identify inputs by element count: preds has N*64 elements,
    // targets has N*2 — pick the larger one as preds.
    int pi = 0, ti = 1;
    if (n_in >= 2 && in_sizes[1] > in_sizes[0]) { pi = 1; ti = 0; }

    const float* preds   = (const float*)d_in[pi];
    const int2*  targets = (const int2*)d_in[ti];
    float*       out     = (float*)d_out;

    const int n = in_sizes[ti] / 2;   // number of rows

    int blocks = (n + WARPS_PER_BLOCK - 1) / WARPS_PER_BLOCK;
    if (blocks > MAX_BLOCKS) blocks = MAX_BLOCKS;
    const int total_warps = blocks * WARPS_PER_BLOCK;

    survival_loss_kernel<<<blocks, THREADS>>>(preds, targets, n, total_warps);
    survival_loss_reduce<<<1, 1024>>>(out, blocks, n);
}

// round 6
// speedup vs baseline: 2.7851x; 2.7851x over previous
#include <cuda_runtime.h>
#include <cuda_bf16.h>

// Survival cross-entropy loss (see reference):
//   loss_i = sum_{j<=t} -log(1-h_j)  +  (event ? (log(1-h_t) - log(h_t)) : 0)
// h = clamp(preds, 1e-9, 1-1e-9). Output = sum(loss_i)/n.
//
// targets are int32 pairs (JAX x64 disabled).
//
// Warp-per-row, lane owns cols [2*lane, 2*lane+1] via one float2 load,
// predicated off for cols > t (saves ~44% of pred DRAM sectors).
// Pair trick: one __logf of the masked product per lane instead of two.
// Contiguous row chunks per warp + unroll-4 for MLP; no shuffles for the
// target broadcast (same-address LDG is a HW broadcast).

#define THREADS 256
#define WARPS_PER_BLOCK (THREADS / 32)
#define NUM_BLOCKS 1184
#define TOTAL_WARPS (NUM_BLOCKS * WARPS_PER_BLOCK)

__device__ float g_partials[NUM_BLOCKS];

__device__ __forceinline__ float row_contrib(const float* __restrict__ preds,
                                             const int2* __restrict__ targets,
                                             int row, int lane)
{
    int2 te = __ldg(&targets[row]);          // same addr across warp -> broadcast
    int  t  = min(max(te.x, 0), 63);
    bool ev = (te.y != 0);
    const int c0 = lane * 2;

    float contrib = 0.0f;
    if (c0 <= t) {
        float2 v = __ldg((const float2*)(preds + (long long)row * 64) + lane);

        float h0 = fminf(fmaxf(v.x, 1e-9f), 0.99999994f);
        float h1 = fminf(fmaxf(v.y, 1e-9f), 0.99999994f);
        float m0 = 1.0f - h0;
        float m1 = (c0 + 1 <= t) ? (1.0f - h1) : 1.0f;

        contrib = -__logf(m0 * m1);

        if (ev) {
            if (c0 == t)          contrib += __logf(m0) - __logf(h0);
            else if (c0 + 1 == t) contrib += __logf(m1) - __logf(h1);
        }
    }
    return contrib;
}

__global__ void __launch_bounds__(THREADS)
survival_loss_kernel(const float* __restrict__ preds,
                     const int2* __restrict__ targets,
                     int n)
{
    const int lane    = threadIdx.x & 31;
    const int warp_in = threadIdx.x >> 5;
    const int w       = blockIdx.x * WARPS_PER_BLOCK + warp_in;

    // contiguous chunk of rows per warp (targets land in few L1 lines,
    // preds stream linearly)
    const int per = (n + TOTAL_WARPS - 1) / TOTAL_WARPS;
    int r0 = w * per;
    int r1 = min(n, r0 + per);

    float acc = 0.0f;

    int row = r0;
    // unroll by 4: independent rows -> front-batched loads, MLP ~8/warp
    for (; row + 3 < r1; row += 4) {
        float a = row_contrib(preds, targets, row + 0, lane);
        float b = row_contrib(preds, targets, row + 1, lane);
        float c = row_contrib(preds, targets, row + 2, lane);
        float d = row_contrib(preds, targets, row + 3, lane);
        acc += (a + b) + (c + d);
    }
    for (; row < r1; row++)
        acc += row_contrib(preds, targets, row, lane);

    // warp reduction
    #pragma unroll
    for (int off = 16; off > 0; off >>= 1)
        acc += __shfl_xor_sync(0xFFFFFFFFu, acc, off);

    __shared__ float warp_sums[WARPS_PER_BLOCK];
    if (lane == 0) warp_sums[warp_in] = acc;
    __syncthreads();

    if (threadIdx.x == 0) {
        float s = 0.0f;
        #pragma unroll
        for (int i = 0; i < WARPS_PER_BLOCK; i++) s += warp_sums[i];
        g_partials[blockIdx.x] = s;
    }
}

__global__ void __launch_bounds__(1024)
survival_loss_reduce(float* __restrict__ out, int n)
{
    __shared__ double sh[1024];
    double s = 0.0;
    for (int i = threadIdx.x; i < NUM_BLOCKS; i += 1024)
        s += (double)g_partials[i];
    sh[threadIdx.x] = s;
    __syncthreads();
    #pragma unroll
    for (int off = 512; off > 0; off >>= 1) {
        if (threadIdx.x < off) sh[threadIdx.x] += sh[threadIdx.x + off];
        __syncthreads();
    }
    if (threadIdx.x == 0)
        out[0] = (float)(sh[0] / (double)n);
}

extern "C" void kernel_launch(void* const* d_in, const int* in_sizes, int n_in,
                              void* d_out, int out_size)
{
    // Identify inputs by element count: preds has N*64 elements, targets N*2.
    int pi = 0, ti = 1;
    if (n_in >= 2 && in_sizes[1] > in_sizes[0]) { pi = 1; ti = 0; }

    const float* preds   = (const float*)d_in[pi];
    const int2*  targets = (const int2*)d_in[ti];
    float*       out     = (float*)d_out;

    const int n = in_sizes[ti] / 2;

    survival_loss_kernel<<<NUM_BLOCKS, THREADS>>>(preds, targets, n);
    survival_loss_reduce<<<1, 1024>>>(out, n);
}

// round 7
// speedup vs baseline: 3.3660x; 1.2086x over previous
#include <cuda_runtime.h>
#include <cuda_bf16.h>

// Survival cross-entropy loss:
//   loss_i = sum_{j<=t} -log(1-h_j)  +  (event ? (log(1-h_t) - log(h_t)) : 0)
// h = clamp(preds, 1e-9, 1-1e-9); out = sum(loss_i)/n.
// targets are int32 (duration, event) pairs (JAX x64 disabled).
//
// Warp-per-row, lane owns cols [2*lane, 2*lane+1] (one float2 load,
// predicated off for cols > t: saves ~44% of pred DRAM sectors).
// Unroll 8 rows: 8 target loads batched, then 8 predicated pred loads
// batched -> MLP ~16/warp. Single kernel; last block does the final
// deterministic reduce (threadfence + counter pattern).

#define THREADS 256
#define WPB (THREADS / 32)
#define NUM_BLOCKS 592            // 4 blocks/SM on 148 SMs -> one wave
#define TOTAL_WARPS (NUM_BLOCKS * WPB)
#define UNROLL 8

__device__ float        g_partials[NUM_BLOCKS];
__device__ unsigned int g_count;   // zero-initialized; reset by last block

__device__ __forceinline__ float calc(float2 v, int t, int ev, int c0, int lane)
{
    if (c0 > t) return 0.0f;
    float h0 = fminf(fmaxf(v.x, 1e-9f), 0.99999994f);
    float h1 = fminf(fmaxf(v.y, 1e-9f), 0.99999994f);
    float m0 = 1.0f - h0;
    float m1 = (c0 + 1 <= t) ? (1.0f - h1) : 1.0f;

    float c = -__logf(m0 * m1);

    // event correction: only the lane holding column t participates
    if (ev && (t >> 1) == lane) {
        float ht = (t & 1) ? h1 : h0;
        float mt = (t & 1) ? m1 : m0;   // t==c0+1 => m1 is the real 1-h1
        c += __logf(mt) - __logf(ht);
    }
    return c;
}

__global__ void __launch_bounds__(THREADS)
survival_loss_kernel(const float* __restrict__ preds,
                     const int2* __restrict__ targets,
                     float* __restrict__ out, int n)
{
    const int lane    = threadIdx.x & 31;
    const int warp_in = threadIdx.x >> 5;
    const int w       = blockIdx.x * WPB + warp_in;
    const int c0      = lane * 2;

    // contiguous chunk of rows per warp
    const int per = (n + TOTAL_WARPS - 1) / TOTAL_WARPS;
    const int r0  = min(n, w * per);
    const int r1  = min(n, r0 + per);

    float acc = 0.0f;

    int row = r0;
    for (; row + (UNROLL - 1) < r1; row += UNROLL) {
        int2 te[UNROLL];
        #pragma unroll
        for (int i = 0; i < UNROLL; i++)
            te[i] = __ldg(&targets[row + i]);     // same addr per warp -> broadcast

        int t[UNROLL];
        float2 v[UNROLL];
        #pragma unroll
        for (int i = 0; i < UNROLL; i++) {
            t[i] = min(max(te[i].x, 0), 63);
            v[i] = make_float2(0.5f, 0.5f);
            if (c0 <= t[i])
                v[i] = __ldg((const float2*)(preds + (size_t)(row + i) * 64) + lane);
        }

        #pragma unroll
        for (int i = 0; i < UNROLL; i++)
            acc += calc(v[i], t[i], te[i].y, c0, lane);
    }
    for (; row < r1; row++) {
        int2 te = __ldg(&targets[row]);
        int  t  = min(max(te.x, 0), 63);
        float2 v = make_float2(0.5f, 0.5f);
        if (c0 <= t)
            v = __ldg((const float2*)(preds + (size_t)row * 64) + lane);
        acc += calc(v, t, te.y, c0, lane);
    }

    // warp reduction
    #pragma unroll
    for (int off = 16; off > 0; off >>= 1)
        acc += __shfl_xor_sync(0xFFFFFFFFu, acc, off);

    __shared__ float warp_sums[WPB];
    __shared__ bool  is_last;
    if (lane == 0) warp_sums[warp_in] = acc;
    __syncthreads();

    if (threadIdx.x == 0) {
        float s = 0.0f;
        #pragma unroll
        for (int i = 0; i < WPB; i++) s += warp_sums[i];
        g_partials[blockIdx.x] = s;
        __threadfence();
        unsigned int prev = atomicAdd(&g_count, 1u);
        is_last = (prev == NUM_BLOCKS - 1);
    }
    __syncthreads();

    if (is_last) {
        // final deterministic reduce (fixed assignment, fixed tree order)
        __shared__ double sh[THREADS];
        double s = 0.0;
        for (int i = threadIdx.x; i < NUM_BLOCKS; i += THREADS)
            s += (double)g_partials[i];
        sh[threadIdx.x] = s;
        __syncthreads();
        #pragma unroll
        for (int off = THREADS / 2; off > 0; off >>= 1) {
            if (threadIdx.x < off) sh[threadIdx.x] += sh[threadIdx.x + off];
            __syncthreads();
        }
        if (threadIdx.x == 0) {
            out[0] = (float)(sh[0] / (double)n);
            g_count = 0;   // reset for next graph replay
        }
    }
}

extern "C" void kernel_launch(void* const* d_in, const int* in_sizes, int n_in,
                              void* d_out, int out_size)
{
    // Identify inputs by element count: preds has N*64 elements, targets N*2.
    int pi = 0, ti = 1;
    if (n_in >= 2 && in_sizes[1] > in_sizes[0]) { pi = 1; ti = 0; }

    const float* preds   = (const float*)d_in[pi];
    const int2*  targets = (const int2*)d_in[ti];
    float*       out     = (float*)d_out;

    const int n = in_sizes[ti] / 2;

    survival_loss_kernel<<<NUM_BLOCKS, THREADS>>>(preds, targets, out, n);
}

// round 8
// speedup vs baseline: 3.6728x; 1.0911x over previous
#include <cuda_runtime.h>
#include <cuda_bf16.h>

// Survival cross-entropy loss:
//   loss_i = sum_{j<=t} -log(1-h_j)  +  (event ? (log(1-h_t) - log(h_t)) : 0)
// h = clamp(preds, 1e-9, 1-1e-9); out = sum(loss_i)/n.
// targets are int32 (duration, event) pairs.
//
// Branch-free folding: the event correction cancels algebraically into the
// log argument of the lane owning column t:
//   t even, event:  -log(m0)              -> -log(h0)
//   t odd,  event:  -log(m0*m1)           -> -log(m0*h1)
// Predicated-off lanes use v=(0,0) -> m=1 -> product 1 -> contributes 0.
// Pairs of rows share one __logf (product can't underflow: >= 3.6e-33).

#define THREADS 256
#define WPB (THREADS / 32)
#define NUM_BLOCKS 592            // 4 blocks/SM on 148 SMs -> one wave
#define TOTAL_WARPS (NUM_BLOCKS * WPB)
#define UNROLL 8

__device__ float        g_partials[NUM_BLOCKS];
__device__ unsigned int g_count;   // zero-init; reset by last block each run

// per-row product argument for this lane (log taken later, pairwise)
__device__ __forceinline__ float row_prod(float2 v, int t, int ev, int c0)
{
    float m0 = 1.0f - v.x;
    float m1 = 1.0f - v.y;
    bool  e0 = (ev != 0) && (t == c0);
    bool  e1 = (ev != 0) && (t == c0 + 1);
    float s0 = e0 ? fmaxf(v.x, 1e-9f) : m0;
    float s1 = (c0 + 1 > t) ? 1.0f : (e1 ? fmaxf(v.y, 1e-9f) : m1);
    return s0 * s1;
}

__global__ void __launch_bounds__(THREADS)
survival_loss_kernel(const float* __restrict__ preds,
                     const int2* __restrict__ targets,
                     float* __restrict__ out, int n)
{
    const int lane    = threadIdx.x & 31;
    const int warp_in = threadIdx.x >> 5;
    const int w       = blockIdx.x * WPB + warp_in;
    const int c0      = lane * 2;

    const int per = (n + TOTAL_WARPS - 1) / TOTAL_WARPS;
    const int r0  = min(n, w * per);
    const int r1  = min(n, r0 + per);

    float acc = 0.0f;

    int row = r0;
    for (; row + (UNROLL - 1) < r1; row += UNROLL) {
        const float2* base = (const float2*)(preds + (size_t)row * 64) + lane;

        int2 te[UNROLL];
        #pragma unroll
        for (int i = 0; i < UNROLL; i++)
            te[i] = __ldg(&targets[row + i]);     // same addr per warp -> broadcast

        int t[UNROLL];
        float2 v[UNROLL];
        #pragma unroll
        for (int i = 0; i < UNROLL; i++) {
            t[i] = min(max(te[i].x, 0), 63);
            v[i] = make_float2(0.0f, 0.0f);        // -> m=1 -> contributes 0
            if (c0 <= t[i])
                v[i] = __ldg(base + i * 32);       // 32 float2 = one row stride
        }

        float p[UNROLL];
        #pragma unroll
        for (int i = 0; i < UNROLL; i++)
            p[i] = row_prod(v[i], t[i], te[i].y, c0);

        // one log per 2 rows
        #pragma unroll
        for (int i = 0; i < UNROLL; i += 2)
            acc -= __logf(p[i] * p[i + 1]);
    }
    for (; row < r1; row++) {
        int2 te = __ldg(&targets[row]);
        int  t  = min(max(te.x, 0), 63);
        float2 v = make_float2(0.0f, 0.0f);
        if (c0 <= t)
            v = __ldg((const float2*)(preds + (size_t)row * 64) + lane);
        acc -= __logf(row_prod(v, t, te.y, c0));
    }

    // warp reduction
    #pragma unroll
    for (int off = 16; off > 0; off >>= 1)
        acc += __shfl_xor_sync(0xFFFFFFFFu, acc, off);

    __shared__ float warp_sums[WPB];
    __shared__ bool  is_last;
    if (lane == 0) warp_sums[warp_in] = acc;
    __syncthreads();

    if (threadIdx.x == 0) {
        float s = 0.0f;
        #pragma unroll
        for (int i = 0; i < WPB; i++) s += warp_sums[i];
        g_partials[blockIdx.x] = s;
        __threadfence();
        unsigned int prev = atomicAdd(&g_count, 1u);
        is_last = (prev == NUM_BLOCKS - 1);
    }
    __syncthreads();

    if (is_last) {
        __shared__ double sh[THREADS];
        double s = 0.0;
        for (int i = threadIdx.x; i < NUM_BLOCKS; i += THREADS)
            s += (double)g_partials[i];
        sh[threadIdx.x] = s;
        __syncthreads();
        #pragma unroll
        for (int off = THREADS / 2; off > 0; off >>= 1) {
            if (threadIdx.x < off) sh[threadIdx.x] += sh[threadIdx.x + off];
            __syncthreads();
        }
        if (threadIdx.x == 0) {
            out[0] = (float)(sh[0] / (double)n);
            g_count = 0;   // reset for next graph replay
        }
    }
}

extern "C" void kernel_launch(void* const* d_in, const int* in_sizes, int n_in,
                              void* d_out, int out_size)
{
    int pi = 0, ti = 1;
    if (n_in >= 2 && in_sizes[1] > in_sizes[0]) { pi = 1; ti = 0; }

    const float* preds   = (const float*)d_in[pi];
    const int2*  targets = (const int2*)d_in[ti];
    float*       out     = (float*)d_out;

    const int n = in_sizes[ti] / 2;

    survival_loss_kernel<<<NUM_BLOCKS, THREADS>>>(preds, targets, out, n);
}

// round 9
// speedup vs baseline: 4.6589x; 1.2685x over previous
#include <cuda_runtime.h>
#include <cuda_bf16.h>

// Survival cross-entropy loss:
//   loss_i = sum_{j<=t} -log(1-h_j)  +  (event ? (log(1-h_t) - log(h_t)) : 0)
// h = clamp(preds, 1e-9, 1-1e-9); out = sum(loss_i)/n.
// targets are int32 (duration, event) pairs.
//
// Branch-free folding of the event correction into the log argument of the
// lane owning column t (t even -> h0; t odd -> m0*h1). Predicated-off lanes
// use v=(0,0) -> m=1 -> contributes 0. One __logf per 2 rows.
//
// 1184 blocks = 8 blocks/SM = 2048 threads/SM (full occupancy; kernel is
// 32 regs/thread, exactly the 64K-reg budget).

#define THREADS 256
#define WPB (THREADS / 32)
#define NUM_BLOCKS 1184           // 8 blocks/SM on 148 SMs -> one full wave
#define TOTAL_WARPS (NUM_BLOCKS * WPB)
#define UNROLL 8

__device__ float        g_partials[NUM_BLOCKS];
__device__ unsigned int g_count;   // zero-init; reset by last block each run

// per-row product argument for this lane (log taken later, pairwise)
__device__ __forceinline__ float row_prod(float2 v, int t, int ev, int c0)
{
    float m0 = 1.0f - v.x;
    float m1 = 1.0f - v.y;
    bool  e0 = (ev != 0) && (t == c0);
    bool  e1 = (ev != 0) && (t == c0 + 1);
    float s0 = e0 ? fmaxf(v.x, 1e-9f) : m0;
    float s1 = (c0 + 1 > t) ? 1.0f : (e1 ? fmaxf(v.y, 1e-9f) : m1);
    return s0 * s1;
}

__global__ void __launch_bounds__(THREADS, 8)
survival_loss_kernel(const float* __restrict__ preds,
                     const int2* __restrict__ targets,
                     float* __restrict__ out, int n)
{
    const int lane    = threadIdx.x & 31;
    const int warp_in = threadIdx.x >> 5;
    const int w       = blockIdx.x * WPB + warp_in;
    const int c0      = lane * 2;

    const int per = (n + TOTAL_WARPS - 1) / TOTAL_WARPS;
    const int r0  = min(n, w * per);
    const int r1  = min(n, r0 + per);

    float acc = 0.0f;

    int row = r0;
    for (; row + (UNROLL - 1) < r1; row += UNROLL) {
        const float2* base = (const float2*)(preds + (size_t)row * 64) + lane;

        int2 te[UNROLL];
        #pragma unroll
        for (int i = 0; i < UNROLL; i++)
            te[i] = __ldg(&targets[row + i]);     // same addr per warp -> broadcast

        int t[UNROLL];
        float2 v[UNROLL];
        #pragma unroll
        for (int i = 0; i < UNROLL; i++) {
            t[i] = min(max(te[i].x, 0), 63);
            v[i] = make_float2(0.0f, 0.0f);        // -> m=1 -> contributes 0
            if (c0 <= t[i])
                v[i] = __ldg(base + i * 32);       // 32 float2 = one row stride
        }

        float p[UNROLL];
        #pragma unroll
        for (int i = 0; i < UNROLL; i++)
            p[i] = row_prod(v[i], t[i], te[i].y, c0);

        // one log per 2 rows (product >= 3.6e-33, no underflow)
        #pragma unroll
        for (int i = 0; i < UNROLL; i += 2)
            acc -= __logf(p[i] * p[i + 1]);
    }
    for (; row < r1; row++) {
        int2 te = __ldg(&targets[row]);
        int  t  = min(max(te.x, 0), 63);
        float2 v = make_float2(0.0f, 0.0f);
        if (c0 <= t)
            v = __ldg((const float2*)(preds + (size_t)row * 64) + lane);
        acc -= __logf(row_prod(v, t, te.y, c0));
    }

    // warp reduction
    #pragma unroll
    for (int off = 16; off > 0; off >>= 1)
        acc += __shfl_xor_sync(0xFFFFFFFFu, acc, off);

    __shared__ float warp_sums[WPB];
    __shared__ bool  is_last;
    if (lane == 0) warp_sums[warp_in] = acc;
    __syncthreads();

    if (threadIdx.x == 0) {
        float s = 0.0f;
        #pragma unroll
        for (int i = 0; i < WPB; i++) s += warp_sums[i];
        g_partials[blockIdx.x] = s;
        __threadfence();
        unsigned int prev = atomicAdd(&g_count, 1u);
        is_last = (prev == NUM_BLOCKS - 1);
    }
    __syncthreads();

    if (is_last) {
        __shared__ double sh[THREADS];
        double s = 0.0;
        for (int i = threadIdx.x; i < NUM_BLOCKS; i += THREADS)
            s += (double)g_partials[i];
        sh[threadIdx.x] = s;
        __syncthreads();
        #pragma unroll
        for (int off = THREADS / 2; off > 0; off >>= 1) {
            if (threadIdx.x < off) sh[threadIdx.x] += sh[threadIdx.x + off];
            __syncthreads();
        }
        if (threadIdx.x == 0) {
            out[0] = (float)(sh[0] / (double)n);
            g_count = 0;   // reset for next graph replay
        }
    }
}

extern "C" void kernel_launch(void* const* d_in, const int* in_sizes, int n_in,
                              void* d_out, int out_size)
{
    int pi = 0, ti = 1;
    if (n_in >= 2 && in_sizes[1] > in_sizes[0]) { pi = 1; ti = 0; }

    const float* preds   = (const float*)d_in[pi];
    const int2*  targets = (const int2*)d_in[ti];
    float*       out     = (float*)d_out;

    const int n = in_sizes[ti] / 2;

    survival_loss_kernel<<<NUM_BLOCKS, THREADS>>>(preds, targets, out, n);
}

// round 10
// speedup vs baseline: 5.1791x; 1.1117x over previous
#include <cuda_runtime.h>
#include <cuda_bf16.h>

// Survival cross-entropy loss:
//   loss_i = sum_{j<=t} -log(1-h_j)  +  (event ? (log(1-h_t) - log(h_t)) : 0)
// h = clamp(preds, 1e-9, 1-1e-9); out = sum(loss_i)/n.
// targets: int32 (duration, event) pairs.
//
// Block stages its targets into smem as (t, tev) with tev = ev ? t : 64,
// so the hot loop has no target->pred DRAM dependency chain.
// Warp-per-row, lane owns cols [2*lane, 2*lane+1]; float2 load predicated
// off for c0 > t (v=(0,0) default -> m=1 -> contributes 0).
// Event fold (branch-free, clamp-after-select; m >= 2^-24 > 1e-9 so the
// clamp never alters a real m):
//   s0 = max( (c0==tev)   ? h0 : m0 , 1e-9 )
//   s1 = (t==c0) ? 1 : max( (c0+1==tev) ? h1 : m1 , 1e-9 )
// One __logf per 2 rows (pair product >= 3.6e-33, no underflow).

#define THREADS 256
#define WPB (THREADS / 32)
#define NUM_BLOCKS 1184           // 8 blocks/SM * 148 SMs: one full wave
#define UNROLL 8
#define SMEM_ROWS 1056            // >= ceil(n / NUM_BLOCKS) for n <= 1.25e6

__device__ float        g_partials[NUM_BLOCKS];
__device__ unsigned int g_count;   // zero-init; reset by last block each run

__device__ __forceinline__ float row_prod(float2 v, int t, int tev, int c0)
{
    float m0 = 1.0f - v.x;
    float m1 = 1.0f - v.y;
    float s0 = fmaxf((c0     == tev) ? v.x : m0, 1e-9f);
    float s1a = fmaxf((c0 + 1 == tev) ? v.y : m1, 1e-9f);
    float s1 = (t == c0) ? 1.0f : s1a;
    return s0 * s1;
}

__global__ void __launch_bounds__(THREADS, 8)
survival_loss_kernel(const float* __restrict__ preds,
                     const int2* __restrict__ targets,
                     float* __restrict__ out, int n)
{
    __shared__ int2 sh_te[SMEM_ROWS];     // (t, tev) per row

    const int lane    = threadIdx.x & 31;
    const int warp_in = threadIdx.x >> 5;
    const int c0      = lane * 2;

    const int per_blk = (n + NUM_BLOCKS - 1) / NUM_BLOCKS;
    const int b0      = blockIdx.x * per_blk;
    const int rows    = max(0, min(n - b0, per_blk));
    const int staged  = min(rows, SMEM_ROWS);   // == rows for this dataset

    // stage targets: coalesced, clamp + event-fold off the hot path
    for (int i = threadIdx.x; i < staged; i += THREADS) {
        int2 te = __ldg(&targets[b0 + i]);
        int  t  = min(max(te.x, 0), 63);
        sh_te[i] = make_int2(t, te.y ? t : 64);
    }
    __syncthreads();

    // per-warp contiguous chunk of the staged rows
    const int chunk = (staged + WPB - 1) / WPB;
    const int i0 = min(staged, warp_in * chunk);
    const int i1 = min(staged, i0 + chunk);

    const float2* pbase = (const float2*)(preds + (size_t)(b0 + i0) * 64) + lane;

    float acc0 = 0.0f, acc1 = 0.0f;

    int i = i0;
    for (; i + (UNROLL - 1) < i1; i += UNROLL) {
        const float2* base = pbase + (size_t)(i - i0) * 32;

        int2 tt[UNROLL];
        #pragma unroll
        for (int k = 0; k < UNROLL; k++)
            tt[k] = sh_te[i + k];                 // LDS, cheap

        float2 v[UNROLL];
        #pragma unroll
        for (int k = 0; k < UNROLL; k++) {
            v[k] = make_float2(0.0f, 0.0f);
            if (c0 <= tt[k].x)
                v[k] = __ldg(base + k * 32);      // 32 float2 = one row
        }

        #pragma unroll
        for (int k = 0; k < UNROLL; k += 2) {
            float pa = row_prod(v[k],     tt[k].x,     tt[k].y,     c0);
            float pb = row_prod(v[k + 1], tt[k + 1].x, tt[k + 1].y, c0);
            if (k & 2) acc1 -= __logf(pa * pb);
            else       acc0 -= __logf(pa * pb);
        }
    }
    for (; i < i1; i++) {
        int2 tt = sh_te[i];
        float2 v = make_float2(0.0f, 0.0f);
        if (c0 <= tt.x)
            v = __ldg(pbase + (size_t)(i - i0) * 32);
        acc0 -= __logf(row_prod(v, tt.x, tt.y, c0));
    }
    // robustness only (dead for this dataset): rows beyond smem capacity
    for (int r = staged + warp_in; r < rows; r += WPB) {
        int2 te = __ldg(&targets[b0 + r]);
        int  t  = min(max(te.x, 0), 63);
        int  tev = te.y ? t : 64;
        float2 v = make_float2(0.0f, 0.0f);
        if (c0 <= t)
            v = __ldg((const float2*)(preds + (size_t)(b0 + r) * 64) + lane);
        acc0 -= __logf(row_prod(v, t, tev, c0));
    }

    float acc = acc0 + acc1;
    #pragma unroll
    for (int off = 16; off > 0; off >>= 1)
        acc += __shfl_xor_sync(0xFFFFFFFFu, acc, off);

    __shared__ float warp_sums[WPB];
    __shared__ bool  is_last;
    if (lane == 0) warp_sums[warp_in] = acc;
    __syncthreads();

    if (threadIdx.x == 0) {
        float s = 0.0f;
        #pragma unroll
        for (int k = 0; k < WPB; k++) s += warp_sums[k];
        g_partials[blockIdx.x] = s;
        __threadfence();
        unsigned int prev = atomicAdd(&g_count, 1u);
        is_last = (prev == NUM_BLOCKS - 1);
    }
    __syncthreads();

    if (is_last) {
        __shared__ double sh[THREADS];
        double s = 0.0;
        for (int k = threadIdx.x; k < NUM_BLOCKS; k += THREADS)
            s += (double)g_partials[k];
        sh[threadIdx.x] = s;
        __syncthreads();
        #pragma unroll
        for (int off = THREADS / 2; off > 0; off >>= 1) {
            if (threadIdx.x < off) sh[threadIdx.x] += sh[threadIdx.x + off];
            __syncthreads();
        }
        if (threadIdx.x == 0) {
            out[0] = (float)(sh[0] / (double)n);
            g_count = 0;   // reset for next graph replay
        }
    }
}

extern "C" void kernel_launch(void* const* d_in, const int* in_sizes, int n_in,
                              void* d_out, int out_size)
{
    int pi = 0, ti = 1;
    if (n_in >= 2 && in_sizes[1] > in_sizes[0]) { pi = 1; ti = 0; }

    const float* preds   = (const float*)d_in[pi];
    const int2*  targets = (const int2*)d_in[ti];
    float*       out     = (float*)d_out;

    const int n = in_sizes[ti] / 2;

    survival_loss_kernel<<<NUM_BLOCKS, THREADS>>>(preds, targets, out, n);
}